// round 6
// baseline (speedup 1.0000x reference)
#include <cuda_runtime.h>
#include <cuda_bf16.h>
#include <cstdint>

// ---------------------------------------------------------------------------
// GMDTW (soft-DTW, gamma=1), m1=m2=2048, d=128. log2-domain DP.
// R6: back to PROVEN release/acquire flag sync (R3), but with the acquire
//     issued at group top and branch-checked at group end (latency hidden),
//     plus 3-group slack so the steady-state spin never fires.
// ---------------------------------------------------------------------------

#define M1 2048
#define M2 2048
#define DIM 128
#define NCTA 32
#define CSTR 2176            // padded row stride of cost matrix
#define CPAD 32              // front pad
#define INV_LN2 1.44269504088896340736f
#define LN2F    0.69314718055994530942f

__device__ float g_C[(size_t)M1 * CSTR];
__device__ float g_n1[M1];
__device__ float g_n2[M2];
__device__ float g_bnd[NCTA][4160];
__device__ int   g_prog[NCTA * 32];   // one flag per 128B (no false sharing)

__device__ __forceinline__ float ex2f(float x) {
    float r; asm("ex2.approx.f32 %0, %1;" : "=f"(r) : "f"(x)); return r;
}
__device__ __forceinline__ float lg2f(float x) {
    float r; asm("lg2.approx.f32 %0, %1;" : "=f"(r) : "f"(x)); return r;
}
__device__ __forceinline__ int acq_load(const int* p) {
    int v; asm volatile("ld.global.acquire.gpu.b32 %0, [%1];" : "=r"(v) : "l"(p) : "memory");
    return v;
}
__device__ __forceinline__ void rel_store(int* p, int v) {
    asm volatile("st.global.release.gpu.b32 [%0], %1;" :: "l"(p), "r"(v) : "memory");
}
__device__ __forceinline__ float4 ldcg4(const float* p) {
    float4 v;
    asm volatile("ld.global.cg.v4.f32 {%0,%1,%2,%3}, [%4];"
                 : "=f"(v.x), "=f"(v.y), "=f"(v.z), "=f"(v.w) : "l"(p) : "memory");
    return v;
}
__device__ __forceinline__ void stcg4(float* p, float4 v) {
    asm volatile("st.global.cg.v4.f32 [%0], {%1,%2,%3,%4};"
                 :: "l"(p), "f"(v.x), "f"(v.y), "f"(v.z), "f"(v.w) : "memory");
}

// ---------------------------------------------------------------------------
__global__ void init_k() {
    g_prog[threadIdx.x] = 0;   // <<<1, 1024>>> covers NCTA*32
}

__global__ void __launch_bounds__(256) norms_k(const float* __restrict__ y,
                                               const float* __restrict__ x2) {
    int w = blockIdx.x * 8 + (threadIdx.x >> 5);
    int lane = threadIdx.x & 31;
    if (w >= 2 * M1) return;
    const float* src = (w < M1) ? (y + (size_t)w * DIM) : (x2 + (size_t)(w - M1) * DIM);
    float4 v = ((const float4*)src)[lane];
    float s = v.x * v.x + v.y * v.y + v.z * v.z + v.w * v.w;
#pragma unroll
    for (int o = 16; o; o >>= 1) s += __shfl_xor_sync(0xffffffffu, s, o);
    if (lane == 0) {
        if (w < M1) g_n1[w] = s; else g_n2[w - M1] = s;
    }
}

__global__ void __launch_bounds__(256) gemm_k(const float* __restrict__ A,
                                              const float* __restrict__ B) {
    __shared__ float As[32][68];
    __shared__ float Bs[32][68];
    const int t  = threadIdx.x;
    const int tx = t & 15, ty = t >> 4;
    const int bi = blockIdx.y << 6, bj = blockIdx.x << 6;
    const int lrow = t >> 2;
    const int lk   = (t & 3) << 3;

    float acc[4][4];
#pragma unroll
    for (int u = 0; u < 4; ++u)
#pragma unroll
        for (int v = 0; v < 4; ++v) acc[u][v] = 0.0f;

    const float* Ap = A + (size_t)(bi + lrow) * DIM + lk;
    const float* Bp = B + (size_t)(bj + lrow) * DIM + lk;

    for (int k0 = 0; k0 < DIM; k0 += 32) {
        float4 a0 = *(const float4*)(Ap + k0);
        float4 a1 = *(const float4*)(Ap + k0 + 4);
        float4 b0 = *(const float4*)(Bp + k0);
        float4 b1 = *(const float4*)(Bp + k0 + 4);
        __syncthreads();
        As[lk + 0][lrow] = a0.x; As[lk + 1][lrow] = a0.y;
        As[lk + 2][lrow] = a0.z; As[lk + 3][lrow] = a0.w;
        As[lk + 4][lrow] = a1.x; As[lk + 5][lrow] = a1.y;
        As[lk + 6][lrow] = a1.z; As[lk + 7][lrow] = a1.w;
        Bs[lk + 0][lrow] = b0.x; Bs[lk + 1][lrow] = b0.y;
        Bs[lk + 2][lrow] = b0.z; Bs[lk + 3][lrow] = b0.w;
        Bs[lk + 4][lrow] = b1.x; Bs[lk + 5][lrow] = b1.y;
        Bs[lk + 6][lrow] = b1.z; Bs[lk + 7][lrow] = b1.w;
        __syncthreads();
#pragma unroll
        for (int kk = 0; kk < 32; ++kk) {
            float4 av = *(const float4*)&As[kk][ty << 2];
            float4 bv = *(const float4*)&Bs[kk][tx << 2];
            float a_[4] = {av.x, av.y, av.z, av.w};
            float b_[4] = {bv.x, bv.y, bv.z, bv.w};
#pragma unroll
            for (int u = 0; u < 4; ++u)
#pragma unroll
                for (int v = 0; v < 4; ++v) acc[u][v] += a_[u] * b_[v];
        }
    }

    float4 nb = *(const float4*)&g_n2[bj + (tx << 2)];
#pragma unroll
    for (int u = 0; u < 4; ++u) {
        int i = bi + (ty << 2) + u;
        float na = g_n1[i];
        float4 o;
        o.x = (na + nb.x - 2.0f * acc[u][0]) * INV_LN2;
        o.y = (na + nb.y - 2.0f * acc[u][1]) * INV_LN2;
        o.z = (na + nb.z - 2.0f * acc[u][2]) * INV_LN2;
        o.w = (na + nb.w - 2.0f * acc[u][3]) * INV_LN2;
        *(float4*)&g_C[(size_t)i * CSTR + CPAD + bj + (tx << 2)] = o;
    }
}

// ---------------------------------------------------------------------------
// DP wavefront: 32 single-warp CTAs x 64 rows (2 rows/lane), unrolled x4.
__global__ void __launch_bounds__(32, 1) dp_k(float* __restrict__ out) {
    const int cta  = blockIdx.x;
    const int lane = threadIdx.x;
    const int base = cta * 64;
    const int iA   = base + lane + 1;
    const int iB   = iA + 32;
    const float* pA = &g_C[(size_t)(iA - 1) * CSTR + CPAD] - (iA + 1);
    const float* pB = &g_C[(size_t)(iB - 1) * CSTR + CPAD] - (iB + 1);

    const float INFV = __int_as_float(0x7f800000);
    const float4 INF4 = make_float4(INFV, INFV, INFV, INFV);

    // producer cta publishes chunk [g-2..g+1] then flag g+1 at each group g.
    // flag F (release) => all B[j], j <= F, are final and visible after acquire>=F.
    const int wend    = (cta > 0) ? (base + 2048) : -1;  // last chunk start we read
    const int flagmax = wend + 3;                        // flag needed for that chunk
    int*       myflag = &g_prog[cta * 32];
    const int* pflag  = &g_prog[((cta > 0) ? (cta - 1) : 0) * 32];
    const float* brow = g_bnd[(cta > 0) ? (cta - 1) : 0];
    int known = 0;

    int g = base + 2;                 // group start diagonal (g % 4 == 2)
    int cs = base + 12;               // next boundary chunk to load (= g+10)

    // boundary ring: ch0=[g-2..g+1], ch1=[g+2..g+5], ch2=[g+6..g+9]
    float4 ch0, ch1, ch2;
    if (cta > 0) {
        int need = base + 15 < flagmax ? base + 15 : flagmax;  // covers first top-load too
        do { known = acq_load(pflag); } while (known < need);
        ch0 = ldcg4(brow + base);
        ch1 = ldcg4(brow + base + 4);
        ch2 = ldcg4(brow + base + 8);
    } else {
        ch0 = INF4; ch1 = INF4; ch2 = INF4;
    }

    float rA1 = INFV, rB1 = INFV;
    float uA  = INFV, uB  = INFV;          // previous iteration's up values (=> dg)
    if (cta == 0 && lane == 0) uA = 0.0f;  // R[0][0]=0 feeds dg at k=2
    float p2 = INFV, p3 = INFV;            // publish carry
    float res = INFV;

    // cost ring, depth 3 groups: cX0 = group g, cX1 = g+4, cX2 = g+8
    float cA0[4], cB0[4], cA1[4], cB1[4], cA2[4], cB2[4];
#pragma unroll
    for (int p = 0; p < 4; ++p) {
        cA0[p] = __ldg(pA + g + p);      cB0[p] = __ldg(pB + g + p);
        cA1[p] = __ldg(pA + g + 4 + p);  cB1[p] = __ldg(pB + g + 4 + p);
        cA2[p] = __ldg(pA + g + 8 + p);  cB2[p] = __ldg(pB + g + 8 + p);
    }

#pragma unroll 1
    for (int gi = 0; gi < 529; ++gi, g += 4) {
        // --- group top: acquire in flight (checked at group end), speculative
        //     boundary chunk load (safe: prior group ensured known >= cs+3),
        //     cost loads for group g+12.
        int fnew = 0;
        if (cta > 0) fnew = acq_load(pflag);
        float4 cnew = (cs <= wend) ? ldcg4(brow + cs) : INF4;

        float nA[4], nB[4];
#pragma unroll
        for (int p = 0; p < 4; ++p) {
            nA[p] = __ldg(pA + g + 12 + p);
            nB[p] = __ldg(pB + g + 12 + p);
        }

        float q0, q1;
#pragma unroll
        for (int p = 0; p < 4; ++p) {
            const int k = g + p;
            float bu = (p == 0) ? ch0.y : (p == 1) ? ch0.z : (p == 2) ? ch0.w : ch1.x;

            float sA = __shfl_up_sync(0xffffffffu, rA1, 1);
            float sB = __shfl_up_sync(0xffffffffu, rB1, 1);
            float tA = __shfl_sync(0xffffffffu, rA1, 31);

            float upA = (lane == 0) ? bu : sA;
            float upB = (lane == 0) ? tA : sB;
            float dgA = uA, dgB = uB;

            float costA = cA0[p], costB = cB0[p];

            float mA = fminf(fminf(rA1, dgA), upA);
            float mB = fminf(fminf(rB1, dgB), upB);
            float eA = ex2f(mA - upA) + ex2f(mA - rA1) + ex2f(mA - dgA);
            float eB = ex2f(mB - upB) + ex2f(mB - rB1) + ex2f(mB - dgB);
            float vAv = (costA + mA) - lg2f(eA);
            float vBv = (costB + mB) - lg2f(eB);

            bool vA = (k > iA) & (k <= iA + M2);
            bool vB = (k > iB) & (k <= iB + M2);

            uA = upA; uB = upB;
            rA1 = vA ? vAv : INFV;
            rB1 = vB ? vBv : INFV;

            res = (k == 4096) ? rB1 : res;

            if (p == 0) q0 = rB1;
            if (p == 1) {
                q1 = rB1;
                if (lane == 31) {
                    stcg4(&g_bnd[cta][g - 2], make_float4(p2, p3, q0, q1));
                    rel_store(myflag, g + 1);      // release: data before flag
                }
            }
            if (p == 2) p2 = rB1;
            if (p == 3) p3 = rB1;
        }

        // --- group end: fold acquire, enforce slack for next group's top-load
        //     (chunk g+14 needs flag >= g+17). Steady state: no spin.
        if (cta > 0) {
            if (fnew > known) known = fnew;
            int need = g + 17 < flagmax ? g + 17 : flagmax;
            while (known < need) known = acq_load(pflag);
        }

        // rotate rings
        ch0 = ch1; ch1 = ch2; ch2 = cnew; cs += 4;
#pragma unroll
        for (int p = 0; p < 4; ++p) {
            cA0[p] = cA1[p]; cB0[p] = cB1[p];
            cA1[p] = cA2[p]; cB1[p] = cB2[p];
            cA2[p] = nA[p];  cB2[p] = nB[p];
        }
    }

    if (cta == NCTA - 1 && lane == 31) {
        out[0] = res * LN2F;
    }
}

// ---------------------------------------------------------------------------
extern "C" void kernel_launch(void* const* d_in, const int* in_sizes, int n_in,
                              void* d_out, int out_size) {
    const float* y  = (const float*)d_in[0];
    const float* x2 = (const float*)d_in[1];
    float* out = (float*)d_out;

    init_k<<<1, 1024>>>();
    norms_k<<<512, 256>>>(y, x2);
    gemm_k<<<dim3(M2 / 64, M1 / 64), 256>>>(y, x2);
    dp_k<<<NCTA, 32>>>(out);
}

// round 8
// speedup vs baseline: 1.6807x; 1.6807x over previous
#include <cuda_runtime.h>
#include <cuda_bf16.h>
#include <cstdint>

// ---------------------------------------------------------------------------
// GMDTW (soft-DTW, gamma=1), m1=m2=2048, d=128. log2-domain DP.
// R8 = R7 resubmit (R7 failed on an environmental "device busy" at harness
// init, before any kernel ran; full dataflow re-audited).
//   - adjacent-row pairing: 1 shfl/iter
//   - diagonal-major cost matrix: one coalesced LDG.64 per iter per lane
//   - finite-BIG (1e30) borders: zero validity guards, NaN-free
//   - 8-diag groups, proven release/acquire flag sync, latency-hidden
// ---------------------------------------------------------------------------

#define M1 2048
#define M2 2048
#define DIM 128
#define NCTA 32
#define CPITCH 2080          // floats per diagonal row of Cd
#define CROWS  4120          // diagonal rows (k) incl. prefetch overrun pad
#define BIGF 1e30f
#define INV_LN2 1.44269504088896340736f
#define LN2F    0.69314718055994530942f

__device__ float g_Cd[(size_t)CROWS * CPITCH];  // Cd[k][r] = C[r][k-r-2]*INV_LN2
__device__ float g_n1[M1];
__device__ float g_n2[M2];
__device__ float g_bnd[NCTA][4240];             // g_bnd[w][k] = R~[row 64(w+1)] @ diag k
__device__ int   g_prog[NCTA * 32];             // flag per 128B

__device__ __forceinline__ float ex2f(float x) {
    float r; asm("ex2.approx.f32 %0, %1;" : "=f"(r) : "f"(x)); return r;
}
__device__ __forceinline__ float lg2f(float x) {
    float r; asm("lg2.approx.f32 %0, %1;" : "=f"(r) : "f"(x)); return r;
}
__device__ __forceinline__ int acq_load(const int* p) {
    int v; asm volatile("ld.global.acquire.gpu.b32 %0, [%1];" : "=r"(v) : "l"(p) : "memory");
    return v;
}
__device__ __forceinline__ void rel_store(int* p, int v) {
    asm volatile("st.global.release.gpu.b32 [%0], %1;" :: "l"(p), "r"(v) : "memory");
}
__device__ __forceinline__ float4 ldcg4(const float* p) {
    float4 v;
    asm volatile("ld.global.cg.v4.f32 {%0,%1,%2,%3}, [%4];"
                 : "=f"(v.x), "=f"(v.y), "=f"(v.z), "=f"(v.w) : "l"(p) : "memory");
    return v;
}
__device__ __forceinline__ void stcg4(float* p, float4 v) {
    asm volatile("st.global.cg.v4.f32 [%0], {%1,%2,%3,%4};"
                 :: "l"(p), "f"(v.x), "f"(v.y), "f"(v.z), "f"(v.w) : "memory");
}

// ---------------------------------------------------------------------------
// init: fill Cd with BIG, reset flags
__global__ void __launch_bounds__(1024) initc_k() {
    size_t idx = (size_t)blockIdx.x * 1024 + threadIdx.x;
    const size_t n4 = (size_t)CROWS * CPITCH / 4;
    if (idx < n4) {
        ((float4*)g_Cd)[idx] = make_float4(BIGF, BIGF, BIGF, BIGF);
    }
    if (idx < NCTA * 32) g_prog[idx] = 0;
}

__global__ void __launch_bounds__(256) norms_k(const float* __restrict__ y,
                                               const float* __restrict__ x2) {
    int w = blockIdx.x * 8 + (threadIdx.x >> 5);
    int lane = threadIdx.x & 31;
    if (w >= 2 * M1) return;
    const float* src = (w < M1) ? (y + (size_t)w * DIM) : (x2 + (size_t)(w - M1) * DIM);
    float4 v = ((const float4*)src)[lane];
    float s = v.x * v.x + v.y * v.y + v.z * v.z + v.w * v.w;
#pragma unroll
    for (int o = 16; o; o >>= 1) s += __shfl_xor_sync(0xffffffffu, s, o);
    if (lane == 0) {
        if (w < M1) g_n1[w] = s; else g_n2[w - M1] = s;
    }
}

// GEMM with diagonal-major scatter epilogue:
// value for (r, c) goes to Cd[r+c+2][r]  (cell i=r+1, j=c+1, k=i+j)
__global__ void __launch_bounds__(256) gemm_k(const float* __restrict__ A,
                                              const float* __restrict__ B) {
    __shared__ float As[32][68];
    __shared__ float Bs[32][68];
    const int t  = threadIdx.x;
    const int tx = t & 15, ty = t >> 4;
    const int bi = blockIdx.y << 6, bj = blockIdx.x << 6;
    const int lrow = t >> 2;
    const int lk   = (t & 3) << 3;

    float acc[4][4];
#pragma unroll
    for (int u = 0; u < 4; ++u)
#pragma unroll
        for (int v = 0; v < 4; ++v) acc[u][v] = 0.0f;

    const float* Ap = A + (size_t)(bi + lrow) * DIM + lk;
    const float* Bp = B + (size_t)(bj + lrow) * DIM + lk;

    for (int k0 = 0; k0 < DIM; k0 += 32) {
        float4 a0 = *(const float4*)(Ap + k0);
        float4 a1 = *(const float4*)(Ap + k0 + 4);
        float4 b0 = *(const float4*)(Bp + k0);
        float4 b1 = *(const float4*)(Bp + k0 + 4);
        __syncthreads();
        As[lk + 0][lrow] = a0.x; As[lk + 1][lrow] = a0.y;
        As[lk + 2][lrow] = a0.z; As[lk + 3][lrow] = a0.w;
        As[lk + 4][lrow] = a1.x; As[lk + 5][lrow] = a1.y;
        As[lk + 6][lrow] = a1.z; As[lk + 7][lrow] = a1.w;
        Bs[lk + 0][lrow] = b0.x; Bs[lk + 1][lrow] = b0.y;
        Bs[lk + 2][lrow] = b0.z; Bs[lk + 3][lrow] = b0.w;
        Bs[lk + 4][lrow] = b1.x; Bs[lk + 5][lrow] = b1.y;
        Bs[lk + 6][lrow] = b1.z; Bs[lk + 7][lrow] = b1.w;
        __syncthreads();
#pragma unroll
        for (int kk = 0; kk < 32; ++kk) {
            float4 av = *(const float4*)&As[kk][ty << 2];
            float4 bv = *(const float4*)&Bs[kk][tx << 2];
            float a_[4] = {av.x, av.y, av.z, av.w};
            float b_[4] = {bv.x, bv.y, bv.z, bv.w};
#pragma unroll
            for (int u = 0; u < 4; ++u)
#pragma unroll
                for (int v = 0; v < 4; ++v) acc[u][v] += a_[u] * b_[v];
        }
    }

    float4 nb = *(const float4*)&g_n2[bj + (tx << 2)];
#pragma unroll
    for (int u = 0; u < 4; ++u) {
        int r = bi + (ty << 2) + u;
        float na = g_n1[r];
        float o0 = (na + nb.x - 2.0f * acc[u][0]) * INV_LN2;
        float o1 = (na + nb.y - 2.0f * acc[u][1]) * INV_LN2;
        float o2 = (na + nb.z - 2.0f * acc[u][2]) * INV_LN2;
        float o3 = (na + nb.w - 2.0f * acc[u][3]) * INV_LN2;
        int c = bj + (tx << 2);
        g_Cd[(size_t)(r + c + 2) * CPITCH + r] = o0;
        g_Cd[(size_t)(r + c + 3) * CPITCH + r] = o1;
        g_Cd[(size_t)(r + c + 4) * CPITCH + r] = o2;
        g_Cd[(size_t)(r + c + 5) * CPITCH + r] = o3;
    }
}

// ---------------------------------------------------------------------------
// DP wavefront: 32 single-warp CTAs, 64 rows/CTA, adjacent-pair rows per lane.
__global__ void __launch_bounds__(32, 1) dp_k(float* __restrict__ out) {
    const int cta  = blockIdx.x;
    const int lane = threadIdx.x;
    const int base = cta * 64;
    const bool l0  = (lane == 0);
    const bool l31 = (lane == 31);

    // loop: k = base .. base+2119, 265 groups of 8
    // lane L computes rows iA = base+2L+1, iB = base+2L+2
    // cost at iter k: float2 at Cd[k][base+2L]  (.x -> iA, .y -> iB)
    const float* pcost = g_Cd + (size_t)base * CPITCH + base + 2 * lane;

    const float4 BIG4 = make_float4(BIGF, BIGF, BIGF, BIGF);

    const int  wend    = (cta > 0) ? (base + 2048) : -1;  // last real chunk start
    const int  flagmax = wend + 3;
    int*       myflag  = &g_prog[cta * 32];
    const int* pflag   = &g_prog[((cta > 0) ? (cta - 1) : 0) * 32];
    const float* brow  = g_bnd[(cta > 0) ? (cta - 1) : 0];
    int known = -1000000;

    // boundary chunk ring for group g: c0=[g-4..g-1], c1=[g..g+3], c2=[g+4..g+7]
    float4 c0, c1, c2;
    if (cta > 0) {
        int need = base + 15 < flagmax ? base + 15 : flagmax;
        do { known = acq_load(pflag); } while (known < need);
        c0 = ldcg4(brow + base - 4);
        c1 = ldcg4(brow + base);
        c2 = ldcg4(brow + base + 4);
    } else {
        c0 = BIG4; c1 = BIG4; c2 = BIG4;
        c1.x = 0.0f;                       // virtual B[0] = R[0][0] = 0
    }

    float rA1 = BIGF, rB1 = BIGF;          // own rows @ diag k-1
    float uA  = BIGF, uB  = BIGF;          // carries: dgA = uA, dgB = uB
    float res = BIGF;

    // cost ring: ring[p] holds cost for iter (current group start + p)
    float2 ring[8];
#pragma unroll
    for (int p = 0; p < 8; ++p)
        ring[p] = *(const float2*)(pcost + (size_t)p * CPITCH);
    const float* pn = pcost + (size_t)8 * CPITCH;   // loads for next group

    int g = base;
    float q[8];

#pragma unroll 1
    for (int gi = 0; gi < 265; ++gi, g += 8) {
        // top: acquire in flight; load boundary chunks [g+8], [g+12]
        // (flag >= g+15 was ensured at end of previous group -> loads are safe)
        int fnew = (cta > 0) ? acq_load(pflag) : 0;
        float4 n1 = (g + 8  <= wend) ? ldcg4(brow + g + 8)  : BIG4;
        float4 n2 = (g + 12 <= wend) ? ldcg4(brow + g + 12) : BIG4;

#pragma unroll
        for (int p = 0; p < 8; ++p) {
            // boundary value B[k-1], k = g+p
            float bu = (p == 0) ? c0.w :
                       (p == 1) ? c1.x : (p == 2) ? c1.y :
                       (p == 3) ? c1.z : (p == 4) ? c1.w :
                       (p == 5) ? c2.x : (p == 6) ? c2.y : c2.z;

            float2 cost = ring[p];
            ring[p] = *(const float2*)(pn + (size_t)p * CPITCH);  // iter k+8

            float sup = __shfl_up_sync(0xffffffffu, rB1, 1);
            float upA = l0 ? bu : sup;
            float upB = rA1;               // old value (row iA @ k-1)

            float mA = fminf(fminf(rA1, uA), upA);
            float mB = fminf(fminf(rB1, uB), upB);
            float eA = ex2f(mA - upA) + ex2f(mA - rA1) + ex2f(mA - uA);
            float eB = ex2f(mB - upB) + ex2f(mB - rB1) + ex2f(mB - uB);
            float nAv = (cost.x + mA) - lg2f(eA);
            float nBv = (cost.y + mB) - lg2f(eB);

            uA = upA;
            uB = rA1;
            rA1 = nAv;
            rB1 = nBv;

            q[p] = rB1;
            if (p == 0 && gi == 264) res = rB1;   // k = base+2112 (cta31: 4096)
        }

        // publish B[g..g+7] (lane 31's row = base+64), then flag
        if (l31) {
            stcg4(&g_bnd[cta][g],     make_float4(q[0], q[1], q[2], q[3]));
            stcg4(&g_bnd[cta][g + 4], make_float4(q[4], q[5], q[6], q[7]));
            rel_store(myflag, g + 7);
        }

        // end: fold acquire; ensure next top's loads ([g+16],[g+20]) are published
        if (cta > 0) {
            if (fnew > known) known = fnew;
            int need = g + 23 < flagmax ? g + 23 : flagmax;
            while (known < need) known = acq_load(pflag);
        }

        // rotate boundary ring; advance cost pointer
        c0 = c2; c1 = n1; c2 = n2;
        pn += (size_t)8 * CPITCH;
    }

    if (cta == NCTA - 1 && l31) {
        out[0] = res * LN2F;
    }
}

// ---------------------------------------------------------------------------
extern "C" void kernel_launch(void* const* d_in, const int* in_sizes, int n_in,
                              void* d_out, int out_size) {
    const float* y  = (const float*)d_in[0];
    const float* x2 = (const float*)d_in[1];
    float* out = (float*)d_out;

    const int n4 = (CROWS * CPITCH) / 4;           // 2,142,400
    initc_k<<<(n4 + 1023) / 1024, 1024>>>();
    norms_k<<<512, 256>>>(y, x2);
    gemm_k<<<dim3(M2 / 64, M1 / 64), 256>>>(y, x2);
    dp_k<<<NCTA, 32>>>(out);
}